// round 9
// baseline (speedup 1.0000x reference)
#include <cuda_runtime.h>
#include <math.h>
#include <stdint.h>

// Problem constants
#define Bz   8
#define SQv  1024
#define SKv  1024
#define Dm   512
#define Hh   8
#define HDv  64
#define DFFv 2048
#define Mrows 8192   // B*SQ == B*SK

// Dense GEMM tiling
#define BM 64
#define BN 128
#define BK 16

// ---------------- scratch (static device memory; no runtime allocation) ----------------
__device__ float g_QH[4194304];     // [8192,512]
__device__ float g_KH[4194304];
__device__ float g_VH[4194304];
__device__ float g_ATT[4194304];
__device__ float g_F1[16777216];    // [8192,2048]
__device__ float g_S0[67108864];    // layer-0 pre-softmax scores [B,H,SQ,SK]

// ---------------- tf32 helpers ---------------------------------------------------------
__device__ __forceinline__ unsigned f2tf(float x) {
    unsigned u;
    asm("cvt.rna.tf32.f32 %0, %1;" : "=r"(u) : "f"(x));
    return u;
}

__device__ __forceinline__ void mma_tf32(float c[4], const unsigned a[4], const unsigned b[2]) {
    asm volatile(
        "mma.sync.aligned.m16n8k8.row.col.f32.tf32.tf32.f32 "
        "{%0,%1,%2,%3}, {%4,%5,%6,%7}, {%8,%9}, {%0,%1,%2,%3};\n"
        : "+f"(c[0]), "+f"(c[1]), "+f"(c[2]), "+f"(c[3])
        : "r"(a[0]), "r"(a[1]), "r"(a[2]), "r"(a[3]), "r"(b[0]), "r"(b[1]));
}

// ---------------- block reductions (blockDim.x == 256 assumed) ----------------
__device__ __forceinline__ float blk_sum256(float v) {
    __shared__ float s[8];
    int tid = threadIdx.x;
    #pragma unroll
    for (int o = 16; o > 0; o >>= 1) v += __shfl_xor_sync(0xffffffffu, v, o);
    __syncthreads();
    if ((tid & 31) == 0) s[tid >> 5] = v;
    __syncthreads();
    float r = 0.f;
    #pragma unroll
    for (int i = 0; i < 8; i++) r += s[i];
    return r;
}

// ---------------- dense GEMM (tf32): C = A[M,K] @ W[K,N] + bias (+GELU) ----------------
// CTA 64x128, 128 threads = 4 warps (2m x 2n), warp tile 32x64, BK=16,
// double-buffered smem, one __syncthreads per K-step. Small tiles -> 3-4 CTAs/SM.
template<int ACT>
__global__ __launch_bounds__(128)
void gemm_tf32(const float* __restrict__ A, const float* __restrict__ W,
               const float* __restrict__ bias, float* __restrict__ C,
               int M, int N, int K)
{
    __shared__ unsigned As[2][BM][BK + 4];   // [m][k], stride 20: LDS conflict-free
    __shared__ unsigned Ws[2][BK][BN + 8];   // [k][n], stride 136: LDS conflict-free

    const int tid  = threadIdx.x;
    const int lane = tid & 31, warp = tid >> 5;
    const int wm = (warp >> 1) * 32;
    const int wn = (warp & 1) * 64;
    const int g = lane >> 2, tg = lane & 3;
    const int bm = blockIdx.y * BM, bn = blockIdx.x * BN;

    float acc[2][8][4];
    #pragma unroll
    for (int i = 0; i < 2; i++)
        #pragma unroll
        for (int j = 0; j < 8; j++)
            #pragma unroll
            for (int r = 0; r < 4; r++) acc[i][j][r] = 0.f;

    // loaders: A tile 64x16 = 256 float4 -> 2/thread; W tile 16x128 = 512 float4 -> 4/thread
    float4 aR[2], wR[4];
    #pragma unroll
    for (int i = 0; i < 2; i++) {
        int f = tid + i * 128;
        aR[i] = *(const float4*)&A[(size_t)(bm + (f >> 2)) * K + ((f & 3) * 4)];
    }
    #pragma unroll
    for (int i = 0; i < 4; i++) {
        int f = tid + i * 128;
        wR[i] = *(const float4*)&W[(size_t)(f >> 5) * N + bn + ((f & 31) * 4)];
    }
    #pragma unroll
    for (int i = 0; i < 2; i++) {
        int f = tid + i * 128;
        *(uint4*)&As[0][f >> 2][(f & 3) * 4] =
            make_uint4(f2tf(aR[i].x), f2tf(aR[i].y), f2tf(aR[i].z), f2tf(aR[i].w));
    }
    #pragma unroll
    for (int i = 0; i < 4; i++) {
        int f = tid + i * 128;
        *(uint4*)&Ws[0][f >> 5][(f & 31) * 4] =
            make_uint4(f2tf(wR[i].x), f2tf(wR[i].y), f2tf(wR[i].z), f2tf(wR[i].w));
    }
    __syncthreads();

    const int nt = K / BK;
    for (int it = 0; it < nt; it++) {
        const int cur = it & 1;
        if (it + 1 < nt) {
            int kt = (it + 1) * BK;
            #pragma unroll
            for (int i = 0; i < 2; i++) {
                int f = tid + i * 128;
                aR[i] = *(const float4*)&A[(size_t)(bm + (f >> 2)) * K + kt + ((f & 3) * 4)];
            }
            #pragma unroll
            for (int i = 0; i < 4; i++) {
                int f = tid + i * 128;
                wR[i] = *(const float4*)&W[(size_t)(kt + (f >> 5)) * N + bn + ((f & 31) * 4)];
            }
        }
        #pragma unroll
        for (int ks = 0; ks < BK; ks += 8) {
            unsigned af[2][4], bf[8][2];
            #pragma unroll
            for (int mi = 0; mi < 2; mi++) {
                int r = wm + mi * 16 + g;
                af[mi][0] = As[cur][r][ks + tg];
                af[mi][1] = As[cur][r + 8][ks + tg];
                af[mi][2] = As[cur][r][ks + tg + 4];
                af[mi][3] = As[cur][r + 8][ks + tg + 4];
            }
            #pragma unroll
            for (int nj = 0; nj < 8; nj++) {
                int c = wn + nj * 8 + g;
                bf[nj][0] = Ws[cur][ks + tg][c];
                bf[nj][1] = Ws[cur][ks + tg + 4][c];
            }
            #pragma unroll
            for (int mi = 0; mi < 2; mi++)
                #pragma unroll
                for (int nj = 0; nj < 8; nj++)
                    mma_tf32(acc[mi][nj], af[mi], bf[nj]);
        }
        if (it + 1 < nt) {
            const int nxt = cur ^ 1;
            #pragma unroll
            for (int i = 0; i < 2; i++) {
                int f = tid + i * 128;
                *(uint4*)&As[nxt][f >> 2][(f & 3) * 4] =
                    make_uint4(f2tf(aR[i].x), f2tf(aR[i].y), f2tf(aR[i].z), f2tf(aR[i].w));
            }
            #pragma unroll
            for (int i = 0; i < 4; i++) {
                int f = tid + i * 128;
                *(uint4*)&Ws[nxt][f >> 5][(f & 31) * 4] =
                    make_uint4(f2tf(wR[i].x), f2tf(wR[i].y), f2tf(wR[i].z), f2tf(wR[i].w));
            }
            __syncthreads();
        }
    }

    #pragma unroll
    for (int mi = 0; mi < 2; mi++) {
        #pragma unroll
        for (int nj = 0; nj < 8; nj++) {
            int row = bm + wm + mi * 16 + g;
            int col = bn + wn + nj * 8 + tg * 2;
            float b0 = bias[col], b1 = bias[col + 1];
            float2 v0 = make_float2(acc[mi][nj][0] + b0, acc[mi][nj][1] + b1);
            float2 v1 = make_float2(acc[mi][nj][2] + b0, acc[mi][nj][3] + b1);
            if (ACT == 1) {
                v0.x = 0.5f * v0.x * (1.f + erff(v0.x * 0.7071067811865475f));
                v0.y = 0.5f * v0.y * (1.f + erff(v0.y * 0.7071067811865475f));
                v1.x = 0.5f * v1.x * (1.f + erff(v1.x * 0.7071067811865475f));
                v1.y = 0.5f * v1.y * (1.f + erff(v1.y * 0.7071067811865475f));
            }
            *(float2*)&C[(size_t)row * N + col]       = v0;
            *(float2*)&C[(size_t)(row + 8) * N + col] = v1;
        }
    }
}

// ---------------- fused attention: scores (+prev / +store S0) + online softmax + P@V ---
// CTA = 64 q-rows of one (b,h). 128 threads = 4 warps, each warp owns 16 q-rows.
// K/V double-buffered in smem (buffer 1 overlays the Q staging tile); ONE
// __syncthreads per 32-row K/V tile. Q fragments register-resident.
// layer 0: writes raw scaled scores to outS. layer 1: reads prevS.
__global__ __launch_bounds__(128)
void attn_fused(const float* __restrict__ QH, const float* __restrict__ KH,
                const float* __restrict__ VH, const float* __restrict__ scale,
                const float* __restrict__ extra, int layer,
                const float* __restrict__ prevS, float* __restrict__ outS,
                float* __restrict__ O)
{
    __shared__ unsigned Ks0[32][72];
    __shared__ unsigned Vs0[32][72];
    __shared__ unsigned Ubuf[64][72];    // Q staging; later K/V buffer 1
    __shared__ unsigned Ps[4][16][40];   // per-warp P buffer [q][k]

    const int tid = threadIdx.x;
    const int lane = tid & 31, warp = tid >> 5;
    const int g = lane >> 2, tg = lane & 3;
    const int wq = warp * 16;
    const int bh = blockIdx.y, b = bh >> 3, h = bh & 7;
    const int q0 = blockIdx.x * 64;
    const float* Qb = QH + (size_t)b * SQv * Dm + h * HDv;
    const float* Kb = KH + (size_t)b * SKv * Dm + h * HDv;
    const float* Vb = VH + (size_t)b * SKv * Dm + h * HDv;

    // ---- load Q tile 64x64 into Ubuf, stage fragments to registers ----
    #pragma unroll
    for (int i = 0; i < 8; i++) {
        int f = tid + i * 128;
        int r = f >> 4, c = (f & 15) * 4;
        float4 qv = *(const float4*)&Qb[(size_t)(q0 + r) * Dm + c];
        *(uint4*)&Ubuf[r][c] = make_uint4(f2tf(qv.x), f2tf(qv.y), f2tf(qv.z), f2tf(qv.w));
    }
    __syncthreads();
    unsigned qf[8][4];
    #pragma unroll
    for (int kc = 0; kc < 8; kc++) {
        qf[kc][0] = Ubuf[wq + g][kc * 8 + tg];
        qf[kc][1] = Ubuf[wq + g + 8][kc * 8 + tg];
        qf[kc][2] = Ubuf[wq + g][kc * 8 + tg + 4];
        qf[kc][3] = Ubuf[wq + g + 8][kc * 8 + tg + 4];
    }
    __syncthreads();   // everyone done reading Ubuf; it becomes K/V buffer 1

    float e = extra[layer];
    e = fminf(fmaxf(e, 0.01f), 50.0f);
    const float eff = scale[layer] * e;

    float m0 = -INFINITY, m8 = -INFINITY, l0 = 0.f, l8 = 0.f;
    float oacc[8][4];
    #pragma unroll
    for (int j = 0; j < 8; j++)
        #pragma unroll
        for (int r = 0; r < 4; r++) oacc[j][r] = 0.f;

    // ---- load K/V tile 0 into buffer 0 ----
    float4 kR[4], vR[4];
    #pragma unroll
    for (int i = 0; i < 4; i++) {
        int f = tid + i * 128;
        int r = f >> 4, c = (f & 15) * 4;
        kR[i] = *(const float4*)&Kb[(size_t)r * Dm + c];
        vR[i] = *(const float4*)&Vb[(size_t)r * Dm + c];
    }
    #pragma unroll
    for (int i = 0; i < 4; i++) {
        int f = tid + i * 128;
        int r = f >> 4, c = (f & 15) * 4;
        *(uint4*)&Ks0[r][c] = make_uint4(f2tf(kR[i].x), f2tf(kR[i].y), f2tf(kR[i].z), f2tf(kR[i].w));
        *(uint4*)&Vs0[r][c] = make_uint4(f2tf(vR[i].x), f2tf(vR[i].y), f2tf(vR[i].z), f2tf(vR[i].w));
    }
    __syncthreads();

    unsigned (*K1)[72] = &Ubuf[0];
    unsigned (*V1)[72] = &Ubuf[32];

    const int row0 = q0 + wq + g;
    const size_t srow0 = ((size_t)bh * SQv + row0) * SKv;
    const size_t srow8 = srow0 + (size_t)8 * SKv;

    for (int it = 0; it < 32; it++) {
        const int kt = it * 32;
        unsigned (*Kc)[72] = (it & 1) ? K1 : Ks0;
        unsigned (*Vc)[72] = (it & 1) ? V1 : Vs0;

        // prefetch next K/V tile into registers
        if (it + 1 < 32) {
            int ktn = kt + 32;
            #pragma unroll
            for (int i = 0; i < 4; i++) {
                int f = tid + i * 128;
                int r = f >> 4, c = (f & 15) * 4;
                kR[i] = *(const float4*)&Kb[(size_t)(ktn + r) * Dm + c];
                vR[i] = *(const float4*)&Vb[(size_t)(ktn + r) * Dm + c];
            }
        }

        // ---- scores: s[nj] = Q(16) x K^T(32), d = 64 ----
        float s[4][4];
        #pragma unroll
        for (int j = 0; j < 4; j++)
            #pragma unroll
            for (int r = 0; r < 4; r++) s[j][r] = 0.f;
        #pragma unroll
        for (int kc = 0; kc < 8; kc++) {
            unsigned bf[4][2];
            #pragma unroll
            for (int nj = 0; nj < 4; nj++) {
                int c = nj * 8 + g;
                bf[nj][0] = Kc[c][kc * 8 + tg];
                bf[nj][1] = Kc[c][kc * 8 + tg + 4];
            }
            #pragma unroll
            for (int nj = 0; nj < 4; nj++)
                mma_tf32(s[nj], qf[kc], bf[nj]);
        }

        // ---- scale, add prev / store raw scores ----
        if (prevS) {
            #pragma unroll
            for (int nj = 0; nj < 4; nj++) {
                int col = kt + nj * 8 + tg * 2;
                float2 p0 = *(const float2*)&prevS[srow0 + col];
                float2 p8 = *(const float2*)&prevS[srow8 + col];
                s[nj][0] = fmaf(s[nj][0], eff, p0.x);
                s[nj][1] = fmaf(s[nj][1], eff, p0.y);
                s[nj][2] = fmaf(s[nj][2], eff, p8.x);
                s[nj][3] = fmaf(s[nj][3], eff, p8.y);
            }
        } else {
            #pragma unroll
            for (int nj = 0; nj < 4; nj++) {
                s[nj][0] *= eff; s[nj][1] *= eff; s[nj][2] *= eff; s[nj][3] *= eff;
                int col = kt + nj * 8 + tg * 2;
                *(float2*)&outS[srow0 + col] = make_float2(s[nj][0], s[nj][1]);
                *(float2*)&outS[srow8 + col] = make_float2(s[nj][2], s[nj][3]);
            }
        }

        // ---- online softmax update ----
        float tm0 = -INFINITY, tm8 = -INFINITY;
        #pragma unroll
        for (int nj = 0; nj < 4; nj++) {
            tm0 = fmaxf(tm0, fmaxf(s[nj][0], s[nj][1]));
            tm8 = fmaxf(tm8, fmaxf(s[nj][2], s[nj][3]));
        }
        tm0 = fmaxf(tm0, __shfl_xor_sync(0xffffffffu, tm0, 1));
        tm0 = fmaxf(tm0, __shfl_xor_sync(0xffffffffu, tm0, 2));
        tm8 = fmaxf(tm8, __shfl_xor_sync(0xffffffffu, tm8, 1));
        tm8 = fmaxf(tm8, __shfl_xor_sync(0xffffffffu, tm8, 2));

        float nm0 = fmaxf(m0, tm0), nm8 = fmaxf(m8, tm8);
        float c0 = __expf(m0 - nm0), c8 = __expf(m8 - nm8);
        float rs0 = 0.f, rs8 = 0.f;
        #pragma unroll
        for (int nj = 0; nj < 4; nj++) {
            s[nj][0] = __expf(s[nj][0] - nm0);
            s[nj][1] = __expf(s[nj][1] - nm0);
            s[nj][2] = __expf(s[nj][2] - nm8);
            s[nj][3] = __expf(s[nj][3] - nm8);
            rs0 += s[nj][0] + s[nj][1];
            rs8 += s[nj][2] + s[nj][3];
        }
        rs0 += __shfl_xor_sync(0xffffffffu, rs0, 1);
        rs0 += __shfl_xor_sync(0xffffffffu, rs0, 2);
        rs8 += __shfl_xor_sync(0xffffffffu, rs8, 1);
        rs8 += __shfl_xor_sync(0xffffffffu, rs8, 2);
        l0 = l0 * c0 + rs0;  l8 = l8 * c8 + rs8;
        m0 = nm0;  m8 = nm8;
        #pragma unroll
        for (int nj = 0; nj < 8; nj++) {
            oacc[nj][0] *= c0; oacc[nj][1] *= c0;
            oacc[nj][2] *= c8; oacc[nj][3] *= c8;
        }

        // ---- P: C-layout -> smem -> A-layout fragments (per-warp buffer) ----
        #pragma unroll
        for (int nj = 0; nj < 4; nj++) {
            Ps[warp][g][nj * 8 + tg * 2]         = f2tf(s[nj][0]);
            Ps[warp][g][nj * 8 + tg * 2 + 1]     = f2tf(s[nj][1]);
            Ps[warp][g + 8][nj * 8 + tg * 2]     = f2tf(s[nj][2]);
            Ps[warp][g + 8][nj * 8 + tg * 2 + 1] = f2tf(s[nj][3]);
        }
        __syncwarp();
        unsigned pf[4][4];
        #pragma unroll
        for (int kc = 0; kc < 4; kc++) {
            pf[kc][0] = Ps[warp][g][kc * 8 + tg];
            pf[kc][1] = Ps[warp][g + 8][kc * 8 + tg];
            pf[kc][2] = Ps[warp][g][kc * 8 + tg + 4];
            pf[kc][3] = Ps[warp][g + 8][kc * 8 + tg + 4];
        }

        // ---- O += P(16x32) @ V(32x64) ----
        #pragma unroll
        for (int kc = 0; kc < 4; kc++) {
            unsigned vb[8][2];
            #pragma unroll
            for (int nj = 0; nj < 8; nj++) {
                int c = nj * 8 + g;
                vb[nj][0] = Vc[kc * 8 + tg][c];
                vb[nj][1] = Vc[kc * 8 + tg + 4][c];
            }
            #pragma unroll
            for (int nj = 0; nj < 8; nj++)
                mma_tf32(oacc[nj], pf[kc], vb[nj]);
        }

        // ---- publish next tile into the idle buffer; single sync ----
        if (it + 1 < 32) {
            unsigned (*Kn)[72] = (it & 1) ? Ks0 : K1;
            unsigned (*Vn)[72] = (it & 1) ? Vs0 : V1;
            #pragma unroll
            for (int i = 0; i < 4; i++) {
                int f = tid + i * 128;
                int r = f >> 4, c = (f & 15) * 4;
                *(uint4*)&Kn[r][c] = make_uint4(f2tf(kR[i].x), f2tf(kR[i].y), f2tf(kR[i].z), f2tf(kR[i].w));
                *(uint4*)&Vn[r][c] = make_uint4(f2tf(vR[i].x), f2tf(vR[i].y), f2tf(vR[i].z), f2tf(vR[i].w));
            }
            __syncthreads();
        }
    }

    // ---- finalize: O /= l, write [b, q, h*64 + d] ----
    float i0 = 1.f / l0, i8 = 1.f / l8;
    float* Ob = O + (size_t)b * SQv * Dm + h * HDv;
    #pragma unroll
    for (int nj = 0; nj < 8; nj++) {
        int col = nj * 8 + tg * 2;
        *(float2*)&Ob[(size_t)row0 * Dm + col] =
            make_float2(oacc[nj][0] * i0, oacc[nj][1] * i0);
        *(float2*)&Ob[(size_t)(row0 + 8) * Dm + col] =
            make_float2(oacc[nj][2] * i8, oacc[nj][3] * i8);
    }
}

// ---------------- gated residual + post-LayerNorm (in-place on q) ----------------------
__global__ __launch_bounds__(256)
void addnorm_kernel(float* __restrict__ q, const float* __restrict__ delta,
                    const float* __restrict__ gate, const float* __restrict__ g,
                    const float* __restrict__ bb)
{
    const size_t row = blockIdx.x;
    const int tid = threadIdx.x;
    const float gt = gate[0];
    const float sp = (gt > 20.f) ? gt : log1pf(expf(gt));   // softplus

    float2 x = *(float2*)&q[row * Dm + tid * 2];
    float2 dd = *(const float2*)&delta[row * Dm + tid * 2];
    float y0 = x.x + sp * dd.x;
    float y1 = x.y + sp * dd.y;

    float s = blk_sum256(y0 + y1);
    float mu = s * (1.f / 512.f);
    float s2 = blk_sum256((y0 - mu) * (y0 - mu) + (y1 - mu) * (y1 - mu));
    float inv = rsqrtf(s2 * (1.f / 512.f) + 1e-5f);

    float2 o;
    o.x = (y0 - mu) * inv * g[tid * 2 + 0] + bb[tid * 2 + 0];
    o.y = (y1 - mu) * inv * g[tid * 2 + 1] + bb[tid * 2 + 1];
    *(float2*)&q[row * Dm + tid * 2] = o;
}

// ---------------- launcher -------------------------------------------------------------
extern "C" void kernel_launch(void* const* d_in, const int* in_sizes, int n_in,
                              void* d_out, int out_size)
{
    (void)in_sizes; (void)n_in; (void)out_size;
    const float* q_in  = (const float*)d_in[0];
    const float* k_in  = (const float*)d_in[1];
    const float* v_in  = (const float*)d_in[2];
    const float* WQ    = (const float*)d_in[3];
    const float* bQ    = (const float*)d_in[4];
    const float* WK    = (const float*)d_in[5];
    const float* bK    = (const float*)d_in[6];
    const float* WV    = (const float*)d_in[7];
    const float* bV    = (const float*)d_in[8];
    const float* WO    = (const float*)d_in[9];
    const float* bO    = (const float*)d_in[10];
    const float* Wf1   = (const float*)d_in[11];
    const float* bf1   = (const float*)d_in[12];
    const float* Wf2   = (const float*)d_in[13];
    const float* bf2   = (const float*)d_in[14];
    const float* ln1g  = (const float*)d_in[15];
    const float* ln1b  = (const float*)d_in[16];
    const float* ln2g  = (const float*)d_in[17];
    const float* ln2b  = (const float*)d_in[18];
    const float* scale = (const float*)d_in[19];
    const float* extra = (const float*)d_in[20];
    const float* gA    = (const float*)d_in[21];
    const float* gF    = (const float*)d_in[22];

    float *QH, *KH, *VH, *ATT, *F1, *S0;
    cudaGetSymbolAddress((void**)&QH, g_QH);
    cudaGetSymbolAddress((void**)&KH, g_KH);
    cudaGetSymbolAddress((void**)&VH, g_VH);
    cudaGetSymbolAddress((void**)&ATT, g_ATT);
    cudaGetSymbolAddress((void**)&F1, g_F1);
    cudaGetSymbolAddress((void**)&S0, g_S0);

    float* qbuf = (float*)d_out;   // q lives in d_out the whole time
    cudaMemcpyAsync(qbuf, q_in, (size_t)Mrows * Dm * sizeof(float),
                    cudaMemcpyDeviceToDevice);

    const dim3 gP(Dm / BN, Mrows / BM);        // (4, 128)  N=512 GEMMs
    const dim3 gF1(DFFv / BN, Mrows / BM);     // (16, 128) FFN1

    for (int i = 0; i < 2; i++) {
        const size_t wofD = (size_t)i * Dm * Dm;
        const size_t wofF = (size_t)i * Dm * DFFv;

        gemm_tf32<0><<<gP, 128>>>(qbuf, WQ + wofD, bQ + i * Dm, QH, Mrows, Dm, Dm);
        gemm_tf32<0><<<gP, 128>>>(k_in, WK + wofD, bK + i * Dm, KH, Mrows, Dm, Dm);
        gemm_tf32<0><<<gP, 128>>>(v_in, WV + wofD, bV + i * Dm, VH, Mrows, Dm, Dm);

        // fused scores(+prev/S0) + online softmax + P@V; attn-out overwrites QH
        const float* prev = (i == 0) ? nullptr : S0;
        float* Sout = (i == 0) ? S0 : nullptr;
        attn_fused<<<dim3(SQv / 64, Bz * Hh), 128>>>(QH, KH, VH, scale, extra, i,
                                                     prev, Sout, QH);

        gemm_tf32<0><<<gP, 128>>>(QH, WO + wofD, bO + i * Dm, ATT, Mrows, Dm, Dm);
        addnorm_kernel<<<Mrows, 256>>>(qbuf, ATT, gA + i, ln1g + (size_t)i * Dm, ln1b + (size_t)i * Dm);

        gemm_tf32<1><<<gF1, 128>>>(qbuf, Wf1 + wofF, bf1 + i * DFFv, F1, Mrows, DFFv, Dm);
        gemm_tf32<0><<<gP, 128>>>(F1, Wf2 + wofF, bf2 + i * Dm, ATT, Mrows, Dm, DFFv);
        addnorm_kernel<<<Mrows, 256>>>(qbuf, ATT, gF + i, ln2g + (size_t)i * Dm, ln2b + (size_t)i * Dm);
    }
}

// round 10
// speedup vs baseline: 1.1680x; 1.1680x over previous
#include <cuda_runtime.h>
#include <math.h>
#include <stdint.h>

// Problem constants
#define Bz   8
#define SQv  1024
#define SKv  1024
#define Dm   512
#define Hh   8
#define HDv  64
#define DFFv 2048
#define Mrows 8192   // B*SQ == B*SK

// Dense GEMM tiling
#define BM 128
#define BN 128
#define BK 16

// ---------------- scratch (static device memory; no runtime allocation) ----------------
__device__ float g_QH[4194304];     // [8192,512]
__device__ float g_KH[4194304];
__device__ float g_VH[4194304];
__device__ float g_ATT[4194304];
__device__ float g_F1[16777216];    // [8192,2048]
__device__ float g_S0[67108864];    // layer-0 pre-softmax scores [B,H,SQ,SK]

// ---------------- mma / cp.async helpers ----------------------------------------------
// mma consumes RAW fp32 bit patterns as tf32 (HW truncates low mantissa bits).
__device__ __forceinline__ void mma_tf32(float c[4], const unsigned a[4], const unsigned b[2]) {
    asm volatile(
        "mma.sync.aligned.m16n8k8.row.col.f32.tf32.tf32.f32 "
        "{%0,%1,%2,%3}, {%4,%5,%6,%7}, {%8,%9}, {%0,%1,%2,%3};\n"
        : "+f"(c[0]), "+f"(c[1]), "+f"(c[2]), "+f"(c[3])
        : "r"(a[0]), "r"(a[1]), "r"(a[2]), "r"(a[3]), "r"(b[0]), "r"(b[1]));
}

__device__ __forceinline__ void cp16(void* smem, const void* gmem) {
    unsigned saddr = (unsigned)__cvta_generic_to_shared(smem);
    asm volatile("cp.async.cg.shared.global [%0], [%1], 16;\n" :: "r"(saddr), "l"(gmem));
}

// ---------------- block reductions (blockDim.x == 256 assumed) ----------------
__device__ __forceinline__ float blk_sum256(float v) {
    __shared__ float s[8];
    int tid = threadIdx.x;
    #pragma unroll
    for (int o = 16; o > 0; o >>= 1) v += __shfl_xor_sync(0xffffffffu, v, o);
    __syncthreads();
    if ((tid & 31) == 0) s[tid >> 5] = v;
    __syncthreads();
    float r = 0.f;
    #pragma unroll
    for (int i = 0; i < 8; i++) r += s[i];
    return r;
}

// ---------------- dense GEMM (tf32): C = A[M,K] @ W[K,N] + bias (+GELU) ----------------
// CTA 128x128, 128 threads = 4 warps (2x2), warp tile 64x64, BK=16.
// cp.async double-buffered tile pipeline; raw fp32 bits in smem.
template<int ACT>
__global__ __launch_bounds__(128)
void gemm_tf32(const float* __restrict__ A, const float* __restrict__ W,
               const float* __restrict__ bias, float* __restrict__ C,
               int M, int N, int K)
{
    __shared__ unsigned As[2][BM][BK + 4];   // [m][k], stride 20: LDS conflict-free
    __shared__ unsigned Ws[2][BK][BN + 8];   // [k][n], stride 136: LDS conflict-free

    const int tid  = threadIdx.x;
    const int lane = tid & 31, warp = tid >> 5;
    const int wm = (warp >> 1) * 64;
    const int wn = (warp & 1) * 64;
    const int g = lane >> 2, tg = lane & 3;
    const int bm = blockIdx.y * BM, bn = blockIdx.x * BN;

    float acc[4][8][4];
    #pragma unroll
    for (int i = 0; i < 4; i++)
        #pragma unroll
        for (int j = 0; j < 8; j++)
            #pragma unroll
            for (int r = 0; r < 4; r++) acc[i][j][r] = 0.f;

    auto issue_tile = [&](int t, int st) {
        int kt = t * BK;
        #pragma unroll
        for (int i = 0; i < 4; i++) {
            int f = tid + i * 128;
            cp16(&As[st][f >> 2][(f & 3) * 4],
                 &A[(size_t)(bm + (f >> 2)) * K + kt + (f & 3) * 4]);
        }
        #pragma unroll
        for (int i = 0; i < 4; i++) {
            int f = tid + i * 128;
            cp16(&Ws[st][f >> 5][(f & 31) * 4],
                 &W[(size_t)(kt + (f >> 5)) * N + bn + (f & 31) * 4]);
        }
        asm volatile("cp.async.commit_group;\n");
    };

    const int nt = K / BK;
    issue_tile(0, 0);
    issue_tile(1, 1);

    for (int it = 0; it < nt; it++) {
        const int cur = it & 1;
        if (it + 1 < nt) { asm volatile("cp.async.wait_group 1;\n"); }
        else             { asm volatile("cp.async.wait_group 0;\n"); }
        __syncthreads();

        #pragma unroll
        for (int ks = 0; ks < BK; ks += 8) {
            unsigned af[4][4], bf[8][2];
            #pragma unroll
            for (int mi = 0; mi < 4; mi++) {
                int r = wm + mi * 16 + g;
                af[mi][0] = As[cur][r][ks + tg];
                af[mi][1] = As[cur][r + 8][ks + tg];
                af[mi][2] = As[cur][r][ks + tg + 4];
                af[mi][3] = As[cur][r + 8][ks + tg + 4];
            }
            #pragma unroll
            for (int nj = 0; nj < 8; nj++) {
                int c = wn + nj * 8 + g;
                bf[nj][0] = Ws[cur][ks + tg][c];
                bf[nj][1] = Ws[cur][ks + tg + 4][c];
            }
            #pragma unroll
            for (int mi = 0; mi < 4; mi++)
                #pragma unroll
                for (int nj = 0; nj < 8; nj++)
                    mma_tf32(acc[mi][nj], af[mi], bf[nj]);
        }

        __syncthreads();
        if (it + 2 < nt) issue_tile(it + 2, cur);
    }

    #pragma unroll
    for (int mi = 0; mi < 4; mi++) {
        #pragma unroll
        for (int nj = 0; nj < 8; nj++) {
            int row = bm + wm + mi * 16 + g;
            int col = bn + wn + nj * 8 + tg * 2;
            float b0 = bias[col], b1 = bias[col + 1];
            float2 v0 = make_float2(acc[mi][nj][0] + b0, acc[mi][nj][1] + b1);
            float2 v1 = make_float2(acc[mi][nj][2] + b0, acc[mi][nj][3] + b1);
            if (ACT == 1) {
                v0.x = 0.5f * v0.x * (1.f + erff(v0.x * 0.7071067811865475f));
                v0.y = 0.5f * v0.y * (1.f + erff(v0.y * 0.7071067811865475f));
                v1.x = 0.5f * v1.x * (1.f + erff(v1.x * 0.7071067811865475f));
                v1.y = 0.5f * v1.y * (1.f + erff(v1.y * 0.7071067811865475f));
            }
            *(float2*)&C[(size_t)row * N + col]       = v0;
            *(float2*)&C[(size_t)(row + 8) * N + col] = v1;
        }
    }
}

// ---------------- fused attention: scores (+prev / +store S0) + online softmax + P@V ---
// CTA = 64 q-rows of one (b,h). 128 threads = 4 warps, each warp owns 16 q-rows.
// K/V tiles (32x64) via cp.async double buffer (buffer 1 overlays the Q staging tile).
// Q fragments register-resident; probabilities stay on-chip.
// layer 0: writes raw scaled scores to outS. layer 1: reads prevS.
__global__ __launch_bounds__(128)
void attn_fused(const float* __restrict__ QH, const float* __restrict__ KH,
                const float* __restrict__ VH, const float* __restrict__ scale,
                const float* __restrict__ extra, int layer,
                const float* __restrict__ prevS, float* __restrict__ outS,
                float* __restrict__ O)
{
    __shared__ unsigned Ks0[32][72];
    __shared__ unsigned Vs0[32][72];
    __shared__ unsigned Ubuf[64][72];    // Q staging; later K/V buffer 1
    __shared__ unsigned Ps[4][16][40];   // per-warp P buffer [q][k]

    const int tid = threadIdx.x;
    const int lane = tid & 31, warp = tid >> 5;
    const int g = lane >> 2, tg = lane & 3;
    const int wq = warp * 16;
    const int bh = blockIdx.y, b = bh >> 3, h = bh & 7;
    const int q0 = blockIdx.x * 64;
    const float* Qb = QH + (size_t)b * SQv * Dm + h * HDv;
    const float* Kb = KH + (size_t)b * SKv * Dm + h * HDv;
    const float* Vb = VH + (size_t)b * SKv * Dm + h * HDv;

    unsigned (*K1)[72] = &Ubuf[0];
    unsigned (*V1)[72] = &Ubuf[32];

    auto issue_kv = [&](int t, unsigned (*Kd)[72], unsigned (*Vd)[72]) {
        int kt = t * 32;
        #pragma unroll
        for (int i = 0; i < 4; i++) {
            int f = tid + i * 128;
            int r = f >> 4, c = (f & 15) * 4;
            cp16(&Kd[r][c], &Kb[(size_t)(kt + r) * Dm + c]);
            cp16(&Vd[r][c], &Vb[(size_t)(kt + r) * Dm + c]);
        }
        asm volatile("cp.async.commit_group;\n");
    };

    // kick off K/V tile 0 immediately (overlaps the Q load below)
    issue_kv(0, Ks0, Vs0);

    // ---- load Q tile 64x64 into Ubuf (raw bits), stage fragments to registers ----
    #pragma unroll
    for (int i = 0; i < 8; i++) {
        int f = tid + i * 128;
        int r = f >> 4, c = (f & 15) * 4;
        *(uint4*)&Ubuf[r][c] = *(const uint4*)&Qb[(size_t)(q0 + r) * Dm + c];
    }
    __syncthreads();
    unsigned qf[8][4];
    #pragma unroll
    for (int kc = 0; kc < 8; kc++) {
        qf[kc][0] = Ubuf[wq + g][kc * 8 + tg];
        qf[kc][1] = Ubuf[wq + g + 8][kc * 8 + tg];
        qf[kc][2] = Ubuf[wq + g][kc * 8 + tg + 4];
        qf[kc][3] = Ubuf[wq + g + 8][kc * 8 + tg + 4];
    }
    __syncthreads();   // Ubuf free -> becomes K/V buffer 1
    issue_kv(1, K1, V1);

    float e = extra[layer];
    e = fminf(fmaxf(e, 0.01f), 50.0f);
    const float eff = scale[layer] * e;

    float m0 = -INFINITY, m8 = -INFINITY, l0 = 0.f, l8 = 0.f;
    float oacc[8][4];
    #pragma unroll
    for (int j = 0; j < 8; j++)
        #pragma unroll
        for (int r = 0; r < 4; r++) oacc[j][r] = 0.f;

    const int row0 = q0 + wq + g;
    const size_t srow0 = ((size_t)bh * SQv + row0) * SKv;
    const size_t srow8 = srow0 + (size_t)8 * SKv;

    for (int it = 0; it < 32; it++) {
        const int kt = it * 32;
        unsigned (*Kc)[72] = (it & 1) ? K1 : Ks0;
        unsigned (*Vc)[72] = (it & 1) ? V1 : Vs0;

        if (it < 31) { asm volatile("cp.async.wait_group 1;\n"); }
        else         { asm volatile("cp.async.wait_group 0;\n"); }
        __syncthreads();

        // ---- scores: s[nj] = Q(16) x K^T(32), d = 64 ----
        float s[4][4];
        #pragma unroll
        for (int j = 0; j < 4; j++)
            #pragma unroll
            for (int r = 0; r < 4; r++) s[j][r] = 0.f;
        #pragma unroll
        for (int kc = 0; kc < 8; kc++) {
            unsigned bf[4][2];
            #pragma unroll
            for (int nj = 0; nj < 4; nj++) {
                int c = nj * 8 + g;
                bf[nj][0] = Kc[c][kc * 8 + tg];
                bf[nj][1] = Kc[c][kc * 8 + tg + 4];
            }
            #pragma unroll
            for (int nj = 0; nj < 4; nj++)
                mma_tf32(s[nj], qf[kc], bf[nj]);
        }

        // ---- scale, add prev / store raw scores ----
        if (prevS) {
            #pragma unroll
            for (int nj = 0; nj < 4; nj++) {
                int col = kt + nj * 8 + tg * 2;
                float2 p0 = *(const float2*)&prevS[srow0 + col];
                float2 p8 = *(const float2*)&prevS[srow8 + col];
                s[nj][0] = fmaf(s[nj][0], eff, p0.x);
                s[nj][1] = fmaf(s[nj][1], eff, p0.y);
                s[nj][2] = fmaf(s[nj][2], eff, p8.x);
                s[nj][3] = fmaf(s[nj][3], eff, p8.y);
            }
        } else {
            #pragma unroll
            for (int nj = 0; nj < 4; nj++) {
                s[nj][0] *= eff; s[nj][1] *= eff; s[nj][2] *= eff; s[nj][3] *= eff;
                int col = kt + nj * 8 + tg * 2;
                *(float2*)&outS[srow0 + col] = make_float2(s[nj][0], s[nj][1]);
                *(float2*)&outS[srow8 + col] = make_float2(s[nj][2], s[nj][3]);
            }
        }

        // ---- online softmax update ----
        float tm0 = -INFINITY, tm8 = -INFINITY;
        #pragma unroll
        for (int nj = 0; nj < 4; nj++) {
            tm0 = fmaxf(tm0, fmaxf(s[nj][0], s[nj][1]));
            tm8 = fmaxf(tm8, fmaxf(s[nj][2], s[nj][3]));
        }
        tm0 = fmaxf(tm0, __shfl_xor_sync(0xffffffffu, tm0, 1));
        tm0 = fmaxf(tm0, __shfl_xor_sync(0xffffffffu, tm0, 2));
        tm8 = fmaxf(tm8, __shfl_xor_sync(0xffffffffu, tm8, 1));
        tm8 = fmaxf(tm8, __shfl_xor_sync(0xffffffffu, tm8, 2));

        float nm0 = fmaxf(m0, tm0), nm8 = fmaxf(m8, tm8);
        float c0 = __expf(m0 - nm0), c8 = __expf(m8 - nm8);
        float rs0 = 0.f, rs8 = 0.f;
        #pragma unroll
        for (int nj = 0; nj < 4; nj++) {
            s[nj][0] = __expf(s[nj][0] - nm0);
            s[nj][1] = __expf(s[nj][1] - nm0);
            s[nj][2] = __expf(s[nj][2] - nm8);
            s[nj][3] = __expf(s[nj][3] - nm8);
            rs0 += s[nj][0] + s[nj][1];
            rs8 += s[nj][2] + s[nj][3];
        }
        rs0 += __shfl_xor_sync(0xffffffffu, rs0, 1);
        rs0 += __shfl_xor_sync(0xffffffffu, rs0, 2);
        rs8 += __shfl_xor_sync(0xffffffffu, rs8, 1);
        rs8 += __shfl_xor_sync(0xffffffffu, rs8, 2);
        l0 = l0 * c0 + rs0;  l8 = l8 * c8 + rs8;
        m0 = nm0;  m8 = nm8;
        #pragma unroll
        for (int nj = 0; nj < 8; nj++) {
            oacc[nj][0] *= c0; oacc[nj][1] *= c0;
            oacc[nj][2] *= c8; oacc[nj][3] *= c8;
        }

        // ---- P: C-layout -> smem -> A-layout fragments (per-warp buffer) ----
        #pragma unroll
        for (int nj = 0; nj < 4; nj++) {
            Ps[warp][g][nj * 8 + tg * 2]         = __float_as_uint(s[nj][0]);
            Ps[warp][g][nj * 8 + tg * 2 + 1]     = __float_as_uint(s[nj][1]);
            Ps[warp][g + 8][nj * 8 + tg * 2]     = __float_as_uint(s[nj][2]);
            Ps[warp][g + 8][nj * 8 + tg * 2 + 1] = __float_as_uint(s[nj][3]);
        }
        __syncwarp();
        unsigned pf[4][4];
        #pragma unroll
        for (int kc = 0; kc < 4; kc++) {
            pf[kc][0] = Ps[warp][g][kc * 8 + tg];
            pf[kc][1] = Ps[warp][g + 8][kc * 8 + tg];
            pf[kc][2] = Ps[warp][g][kc * 8 + tg + 4];
            pf[kc][3] = Ps[warp][g + 8][kc * 8 + tg + 4];
        }

        // ---- O += P(16x32) @ V(32x64) ----
        #pragma unroll
        for (int kc = 0; kc < 4; kc++) {
            unsigned vb[8][2];
            #pragma unroll
            for (int nj = 0; nj < 8; nj++) {
                int c = nj * 8 + g;
                vb[nj][0] = Vc[kc * 8 + tg][c];
                vb[nj][1] = Vc[kc * 8 + tg + 4][c];
            }
            #pragma unroll
            for (int nj = 0; nj < 8; nj++)
                mma_tf32(oacc[nj], pf[kc], vb[nj]);
        }

        __syncthreads();   // all warps done reading Kc/Vc
        if (it + 2 < 32) issue_kv(it + 2, Kc, Vc);   // refill the just-freed buffer
    }

    // ---- finalize: O /= l, write [b, q, h*64 + d] ----
    float i0 = 1.f / l0, i8 = 1.f / l8;
    float* Ob = O + (size_t)b * SQv * Dm + h * HDv;
    #pragma unroll
    for (int nj = 0; nj < 8; nj++) {
        int col = nj * 8 + tg * 2;
        *(float2*)&Ob[(size_t)row0 * Dm + col] =
            make_float2(oacc[nj][0] * i0, oacc[nj][1] * i0);
        *(float2*)&Ob[(size_t)(row0 + 8) * Dm + col] =
            make_float2(oacc[nj][2] * i8, oacc[nj][3] * i8);
    }
}

// ---------------- gated residual + post-LayerNorm (in-place on q) ----------------------
__global__ __launch_bounds__(256)
void addnorm_kernel(float* __restrict__ q, const float* __restrict__ delta,
                    const float* __restrict__ gate, const float* __restrict__ g,
                    const float* __restrict__ bb)
{
    const size_t row = blockIdx.x;
    const int tid = threadIdx.x;
    const float gt = gate[0];
    const float sp = (gt > 20.f) ? gt : log1pf(expf(gt));   // softplus

    float2 x = *(float2*)&q[row * Dm + tid * 2];
    float2 dd = *(const float2*)&delta[row * Dm + tid * 2];
    float y0 = x.x + sp * dd.x;
    float y1 = x.y + sp * dd.y;

    float s = blk_sum256(y0 + y1);
    float mu = s * (1.f / 512.f);
    float s2 = blk_sum256((y0 - mu) * (y0 - mu) + (y1 - mu) * (y1 - mu));
    float inv = rsqrtf(s2 * (1.f / 512.f) + 1e-5f);

    float2 o;
    o.x = (y0 - mu) * inv * g[tid * 2 + 0] + bb[tid * 2 + 0];
    o.y = (y1 - mu) * inv * g[tid * 2 + 1] + bb[tid * 2 + 1];
    *(float2*)&q[row * Dm + tid * 2] = o;
}

// ---------------- launcher -------------------------------------------------------------
extern "C" void kernel_launch(void* const* d_in, const int* in_sizes, int n_in,
                              void* d_out, int out_size)
{
    (void)in_sizes; (void)n_in; (void)out_size;
    const float* q_in  = (const float*)d_in[0];
    const float* k_in  = (const float*)d_in[1];
    const float* v_in  = (const float*)d_in[2];
    const float* WQ    = (const float*)d_in[3];
    const float* bQ    = (const float*)d_in[4];
    const float* WK    = (const float*)d_in[5];
    const float* bK    = (const float*)d_in[6];
    const float* WV    = (const float*)d_in[7];
    const float* bV    = (const float*)d_in[8];
    const float* WO    = (const float*)d_in[9];
    const float* bO    = (const float*)d_in[10];
    const float* Wf1   = (const float*)d_in[11];
    const float* bf1   = (const float*)d_in[12];
    const float* Wf2   = (const float*)d_in[13];
    const float* bf2   = (const float*)d_in[14];
    const float* ln1g  = (const float*)d_in[15];
    const float* ln1b  = (const float*)d_in[16];
    const float* ln2g  = (const float*)d_in[17];
    const float* ln2b  = (const float*)d_in[18];
    const float* scale = (const float*)d_in[19];
    const float* extra = (const float*)d_in[20];
    const float* gA    = (const float*)d_in[21];
    const float* gF    = (const float*)d_in[22];

    float *QH, *KH, *VH, *ATT, *F1, *S0;
    cudaGetSymbolAddress((void**)&QH, g_QH);
    cudaGetSymbolAddress((void**)&KH, g_KH);
    cudaGetSymbolAddress((void**)&VH, g_VH);
    cudaGetSymbolAddress((void**)&ATT, g_ATT);
    cudaGetSymbolAddress((void**)&F1, g_F1);
    cudaGetSymbolAddress((void**)&S0, g_S0);

    float* qbuf = (float*)d_out;   // q lives in d_out the whole time
    cudaMemcpyAsync(qbuf, q_in, (size_t)Mrows * Dm * sizeof(float),
                    cudaMemcpyDeviceToDevice);

    const dim3 gP(Dm / BN, Mrows / BM);        // (4, 64)  N=512 GEMMs
    const dim3 gF1(DFFv / BN, Mrows / BM);     // (16, 64) FFN1

    for (int i = 0; i < 2; i++) {
        const size_t wofD = (size_t)i * Dm * Dm;
        const size_t wofF = (size_t)i * Dm * DFFv;

        gemm_tf32<0><<<gP, 128>>>(qbuf, WQ + wofD, bQ + i * Dm, QH, Mrows, Dm, Dm);
        gemm_tf32<0><<<gP, 128>>>(k_in, WK + wofD, bK + i * Dm, KH, Mrows, Dm, Dm);
        gemm_tf32<0><<<gP, 128>>>(v_in, WV + wofD, bV + i * Dm, VH, Mrows, Dm, Dm);

        // fused scores(+prev/S0) + online softmax + P@V; attn-out overwrites QH
        const float* prev = (i == 0) ? nullptr : S0;
        float* Sout = (i == 0) ? S0 : nullptr;
        attn_fused<<<dim3(SQv / 64, Bz * Hh), 128>>>(QH, KH, VH, scale, extra, i,
                                                     prev, Sout, QH);

        gemm_tf32<0><<<gP, 128>>>(QH, WO + wofD, bO + i * Dm, ATT, Mrows, Dm, Dm);
        addnorm_kernel<<<Mrows, 256>>>(qbuf, ATT, gA + i, ln1g + (size_t)i * Dm, ln1b + (size_t)i * Dm);

        gemm_tf32<1><<<gF1, 128>>>(qbuf, Wf1 + wofF, bf1 + i * DFFv, F1, Mrows, DFFv, Dm);
        gemm_tf32<0><<<gP, 128>>>(F1, Wf2 + wofF, bf2 + i * Dm, ATT, Mrows, Dm, DFFv);
        addnorm_kernel<<<Mrows, 256>>>(qbuf, ATT, gF + i, ln2g + (size_t)i * Dm, ln2b + (size_t)i * Dm);
    }
}

// round 11
// speedup vs baseline: 1.2554x; 1.0748x over previous
#include <cuda_runtime.h>
#include <math.h>
#include <stdint.h>

// Problem constants
#define Bz   8
#define SQv  1024
#define SKv  1024
#define Dm   512
#define Hh   8
#define HDv  64
#define DFFv 2048
#define Mrows 8192   // B*SQ == B*SK

// Dense GEMM tiling
#define BM 128
#define BN 128
#define BK 16
#define ASTRIDE (BK + 4)           // 20 words: LDS conflict-free
#define WSTRIDE (BN + 8)           // 136 words: LDS conflict-free
#define ASZ (BM * ASTRIDE)         // 2560 words
#define WSZ (BK * WSTRIDE)         // 2176 words
#define SLOT (ASZ + WSZ)           // 4736 words per pipeline stage
#define GEMM_SMEM (4 * SLOT * 4)   // 75776 bytes (4 stages)

// ---------------- scratch (static device memory; no runtime allocation) ----------------
__device__ float g_QH[4194304];     // [8192,512]
__device__ float g_KH[4194304];
__device__ float g_VH[4194304];
__device__ float g_ATT[4194304];
__device__ float g_F1[16777216];    // [8192,2048]
__device__ float g_S0[67108864];    // layer-0 pre-softmax scores [B,H,SQ,SK]

// ---------------- mma / cp.async helpers ----------------------------------------------
// mma consumes RAW fp32 bit patterns as tf32 (HW truncates low mantissa bits).
__device__ __forceinline__ void mma_tf32(float c[4], const unsigned a[4], const unsigned b[2]) {
    asm volatile(
        "mma.sync.aligned.m16n8k8.row.col.f32.tf32.tf32.f32 "
        "{%0,%1,%2,%3}, {%4,%5,%6,%7}, {%8,%9}, {%0,%1,%2,%3};\n"
        : "+f"(c[0]), "+f"(c[1]), "+f"(c[2]), "+f"(c[3])
        : "r"(a[0]), "r"(a[1]), "r"(a[2]), "r"(a[3]), "r"(b[0]), "r"(b[1]));
}

__device__ __forceinline__ void cp16(void* smem, const void* gmem) {
    unsigned saddr = (unsigned)__cvta_generic_to_shared(smem);
    asm volatile("cp.async.cg.shared.global [%0], [%1], 16;\n" :: "r"(saddr), "l"(gmem));
}

// ---------------- block reductions (blockDim.x == 256 assumed) ----------------
__device__ __forceinline__ float blk_sum256(float v) {
    __shared__ float s[8];
    int tid = threadIdx.x;
    #pragma unroll
    for (int o = 16; o > 0; o >>= 1) v += __shfl_xor_sync(0xffffffffu, v, o);
    __syncthreads();
    if ((tid & 31) == 0) s[tid >> 5] = v;
    __syncthreads();
    float r = 0.f;
    #pragma unroll
    for (int i = 0; i < 8; i++) r += s[i];
    return r;
}

// ---------------- dense GEMM (tf32): C = A[M,K] @ W[K,N] + bias (+GELU) ----------------
// CTA 128x128, 128 threads = 4 warps (2x2), warp tile 64x64, BK=16.
// 4-slot / 3-outstanding cp.async pipeline, ONE __syncthreads per K-step.
// Dynamic smem (75.8 KB).
template<int ACT>
__global__ __launch_bounds__(128)
void gemm_tf32(const float* __restrict__ A, const float* __restrict__ W,
               const float* __restrict__ bias, float* __restrict__ C,
               int M, int N, int K)
{
    extern __shared__ unsigned dynsm[];

    const int tid  = threadIdx.x;
    const int lane = tid & 31, warp = tid >> 5;
    const int wm = (warp >> 1) * 64;
    const int wn = (warp & 1) * 64;
    const int g = lane >> 2, tg = lane & 3;
    const int bm = blockIdx.y * BM, bn = blockIdx.x * BN;

    float acc[4][8][4];
    #pragma unroll
    for (int i = 0; i < 4; i++)
        #pragma unroll
        for (int j = 0; j < 8; j++)
            #pragma unroll
            for (int r = 0; r < 4; r++) acc[i][j][r] = 0.f;

    auto issue_tile = [&](int t, int st) {
        int kt = t * BK;
        unsigned* Ad = dynsm + st * SLOT;
        unsigned* Wd = Ad + ASZ;
        #pragma unroll
        for (int i = 0; i < 4; i++) {
            int f = tid + i * 128;
            cp16(&Ad[(f >> 2) * ASTRIDE + (f & 3) * 4],
                 &A[(size_t)(bm + (f >> 2)) * K + kt + (f & 3) * 4]);
        }
        #pragma unroll
        for (int i = 0; i < 4; i++) {
            int f = tid + i * 128;
            cp16(&Wd[(f >> 5) * WSTRIDE + (f & 31) * 4],
                 &W[(size_t)(kt + (f >> 5)) * N + bn + (f & 31) * 4]);
        }
        asm volatile("cp.async.commit_group;\n");
    };

    const int nt = K / BK;   // >= 32 always
    issue_tile(0, 0);
    issue_tile(1, 1);
    issue_tile(2, 2);

    for (int it = 0; it < nt; it++) {
        // tile `it` must be complete; up to (issued - (it+1)) groups may stay pending
        if (it + 2 < nt)      { asm volatile("cp.async.wait_group 2;\n"); }
        else if (it + 1 < nt) { asm volatile("cp.async.wait_group 1;\n"); }
        else                  { asm volatile("cp.async.wait_group 0;\n"); }
        __syncthreads();

        // refill the slot freed by tile it-1 (all warps passed the barrier above)
        if (it + 3 < nt) issue_tile(it + 3, (it + 3) & 3);

        const unsigned* Asl = dynsm + (it & 3) * SLOT;
        const unsigned* Wsl = Asl + ASZ;

        #pragma unroll
        for (int ks = 0; ks < BK; ks += 8) {
            unsigned af[4][4], bf[8][2];
            #pragma unroll
            for (int mi = 0; mi < 4; mi++) {
                int r = wm + mi * 16 + g;
                af[mi][0] = Asl[r * ASTRIDE + ks + tg];
                af[mi][1] = Asl[(r + 8) * ASTRIDE + ks + tg];
                af[mi][2] = Asl[r * ASTRIDE + ks + tg + 4];
                af[mi][3] = Asl[(r + 8) * ASTRIDE + ks + tg + 4];
            }
            #pragma unroll
            for (int nj = 0; nj < 8; nj++) {
                int c = wn + nj * 8 + g;
                bf[nj][0] = Wsl[(ks + tg) * WSTRIDE + c];
                bf[nj][1] = Wsl[(ks + tg + 4) * WSTRIDE + c];
            }
            #pragma unroll
            for (int mi = 0; mi < 4; mi++)
                #pragma unroll
                for (int nj = 0; nj < 8; nj++)
                    mma_tf32(acc[mi][nj], af[mi], bf[nj]);
        }
    }

    #pragma unroll
    for (int mi = 0; mi < 4; mi++) {
        #pragma unroll
        for (int nj = 0; nj < 8; nj++) {
            int row = bm + wm + mi * 16 + g;
            int col = bn + wn + nj * 8 + tg * 2;
            float b0 = bias[col], b1 = bias[col + 1];
            float2 v0 = make_float2(acc[mi][nj][0] + b0, acc[mi][nj][1] + b1);
            float2 v1 = make_float2(acc[mi][nj][2] + b0, acc[mi][nj][3] + b1);
            if (ACT == 1) {
                v0.x = 0.5f * v0.x * (1.f + erff(v0.x * 0.7071067811865475f));
                v0.y = 0.5f * v0.y * (1.f + erff(v0.y * 0.7071067811865475f));
                v1.x = 0.5f * v1.x * (1.f + erff(v1.x * 0.7071067811865475f));
                v1.y = 0.5f * v1.y * (1.f + erff(v1.y * 0.7071067811865475f));
            }
            *(float2*)&C[(size_t)row * N + col]       = v0;
            *(float2*)&C[(size_t)(row + 8) * N + col] = v1;
        }
    }
}

// ---------------- fused attention: scores (+prev / +store S0) + online softmax + P@V ---
// CTA = 64 q-rows of one (b,h). 128 threads = 4 warps, each warp owns 16 q-rows.
// K/V tiles (32x64) via cp.async double buffer (buffer 1 overlays the Q staging tile).
// Q fragments register-resident; probabilities stay on-chip.
// layer 0: writes raw scaled scores to outS. layer 1: reads prevS.
__global__ __launch_bounds__(128)
void attn_fused(const float* __restrict__ QH, const float* __restrict__ KH,
                const float* __restrict__ VH, const float* __restrict__ scale,
                const float* __restrict__ extra, int layer,
                const float* __restrict__ prevS, float* __restrict__ outS,
                float* __restrict__ O)
{
    __shared__ unsigned Ks0[32][72];
    __shared__ unsigned Vs0[32][72];
    __shared__ unsigned Ubuf[64][72];    // Q staging; later K/V buffer 1
    __shared__ unsigned Ps[4][16][40];   // per-warp P buffer [q][k]

    const int tid = threadIdx.x;
    const int lane = tid & 31, warp = tid >> 5;
    const int g = lane >> 2, tg = lane & 3;
    const int wq = warp * 16;
    const int bh = blockIdx.y, b = bh >> 3, h = bh & 7;
    const int q0 = blockIdx.x * 64;
    const float* Qb = QH + (size_t)b * SQv * Dm + h * HDv;
    const float* Kb = KH + (size_t)b * SKv * Dm + h * HDv;
    const float* Vb = VH + (size_t)b * SKv * Dm + h * HDv;

    unsigned (*K1)[72] = &Ubuf[0];
    unsigned (*V1)[72] = &Ubuf[32];

    auto issue_kv = [&](int t, unsigned (*Kd)[72], unsigned (*Vd)[72]) {
        int kt = t * 32;
        #pragma unroll
        for (int i = 0; i < 4; i++) {
            int f = tid + i * 128;
            int r = f >> 4, c = (f & 15) * 4;
            cp16(&Kd[r][c], &Kb[(size_t)(kt + r) * Dm + c]);
            cp16(&Vd[r][c], &Vb[(size_t)(kt + r) * Dm + c]);
        }
        asm volatile("cp.async.commit_group;\n");
    };

    // kick off K/V tile 0 immediately (overlaps the Q load below)
    issue_kv(0, Ks0, Vs0);

    // ---- load Q tile 64x64 into Ubuf (raw bits), stage fragments to registers ----
    #pragma unroll
    for (int i = 0; i < 8; i++) {
        int f = tid + i * 128;
        int r = f >> 4, c = (f & 15) * 4;
        *(uint4*)&Ubuf[r][c] = *(const uint4*)&Qb[(size_t)(q0 + r) * Dm + c];
    }
    __syncthreads();
    unsigned qf[8][4];
    #pragma unroll
    for (int kc = 0; kc < 8; kc++) {
        qf[kc][0] = Ubuf[wq + g][kc * 8 + tg];
        qf[kc][1] = Ubuf[wq + g + 8][kc * 8 + tg];
        qf[kc][2] = Ubuf[wq + g][kc * 8 + tg + 4];
        qf[kc][3] = Ubuf[wq + g + 8][kc * 8 + tg + 4];
    }
    __syncthreads();   // Ubuf free -> becomes K/V buffer 1
    issue_kv(1, K1, V1);

    float e = extra[layer];
    e = fminf(fmaxf(e, 0.01f), 50.0f);
    const float eff = scale[layer] * e;

    float m0 = -INFINITY, m8 = -INFINITY, l0 = 0.f, l8 = 0.f;
    float oacc[8][4];
    #pragma unroll
    for (int j = 0; j < 8; j++)
        #pragma unroll
        for (int r = 0; r < 4; r++) oacc[j][r] = 0.f;

    const int row0 = q0 + wq + g;
    const size_t srow0 = ((size_t)bh * SQv + row0) * SKv;
    const size_t srow8 = srow0 + (size_t)8 * SKv;

    for (int it = 0; it < 32; it++) {
        const int kt = it * 32;
        unsigned (*Kc)[72] = (it & 1) ? K1 : Ks0;
        unsigned (*Vc)[72] = (it & 1) ? V1 : Vs0;

        if (it < 31) { asm volatile("cp.async.wait_group 1;\n"); }
        else         { asm volatile("cp.async.wait_group 0;\n"); }
        __syncthreads();

        // ---- scores: s[nj] = Q(16) x K^T(32), d = 64 ----
        float s[4][4];
        #pragma unroll
        for (int j = 0; j < 4; j++)
            #pragma unroll
            for (int r = 0; r < 4; r++) s[j][r] = 0.f;
        #pragma unroll
        for (int kc = 0; kc < 8; kc++) {
            unsigned bf[4][2];
            #pragma unroll
            for (int nj = 0; nj < 4; nj++) {
                int c = nj * 8 + g;
                bf[nj][0] = Kc[c][kc * 8 + tg];
                bf[nj][1] = Kc[c][kc * 8 + tg + 4];
            }
            #pragma unroll
            for (int nj = 0; nj < 4; nj++)
                mma_tf32(s[nj], qf[kc], bf[nj]);
        }

        // ---- scale, add prev / store raw scores ----
        if (prevS) {
            #pragma unroll
            for (int nj = 0; nj < 4; nj++) {
                int col = kt + nj * 8 + tg * 2;
                float2 p0 = *(const float2*)&prevS[srow0 + col];
                float2 p8 = *(const float2*)&prevS[srow8 + col];
                s[nj][0] = fmaf(s[nj][0], eff, p0.x);
                s[nj][1] = fmaf(s[nj][1], eff, p0.y);
                s[nj][2] = fmaf(s[nj][2], eff, p8.x);
                s[nj][3] = fmaf(s[nj][3], eff, p8.y);
            }
        } else {
            #pragma unroll
            for (int nj = 0; nj < 4; nj++) {
                s[nj][0] *= eff; s[nj][1] *= eff; s[nj][2] *= eff; s[nj][3] *= eff;
                int col = kt + nj * 8 + tg * 2;
                *(float2*)&outS[srow0 + col] = make_float2(s[nj][0], s[nj][1]);
                *(float2*)&outS[srow8 + col] = make_float2(s[nj][2], s[nj][3]);
            }
        }

        // ---- online softmax update ----
        float tm0 = -INFINITY, tm8 = -INFINITY;
        #pragma unroll
        for (int nj = 0; nj < 4; nj++) {
            tm0 = fmaxf(tm0, fmaxf(s[nj][0], s[nj][1]));
            tm8 = fmaxf(tm8, fmaxf(s[nj][2], s[nj][3]));
        }
        tm0 = fmaxf(tm0, __shfl_xor_sync(0xffffffffu, tm0, 1));
        tm0 = fmaxf(tm0, __shfl_xor_sync(0xffffffffu, tm0, 2));
        tm8 = fmaxf(tm8, __shfl_xor_sync(0xffffffffu, tm8, 1));
        tm8 = fmaxf(tm8, __shfl_xor_sync(0xffffffffu, tm8, 2));

        float nm0 = fmaxf(m0, tm0), nm8 = fmaxf(m8, tm8);
        float c0 = __expf(m0 - nm0), c8 = __expf(m8 - nm8);
        float rs0 = 0.f, rs8 = 0.f;
        #pragma unroll
        for (int nj = 0; nj < 4; nj++) {
            s[nj][0] = __expf(s[nj][0] - nm0);
            s[nj][1] = __expf(s[nj][1] - nm0);
            s[nj][2] = __expf(s[nj][2] - nm8);
            s[nj][3] = __expf(s[nj][3] - nm8);
            rs0 += s[nj][0] + s[nj][1];
            rs8 += s[nj][2] + s[nj][3];
        }
        rs0 += __shfl_xor_sync(0xffffffffu, rs0, 1);
        rs0 += __shfl_xor_sync(0xffffffffu, rs0, 2);
        rs8 += __shfl_xor_sync(0xffffffffu, rs8, 1);
        rs8 += __shfl_xor_sync(0xffffffffu, rs8, 2);
        l0 = l0 * c0 + rs0;  l8 = l8 * c8 + rs8;
        m0 = nm0;  m8 = nm8;
        #pragma unroll
        for (int nj = 0; nj < 8; nj++) {
            oacc[nj][0] *= c0; oacc[nj][1] *= c0;
            oacc[nj][2] *= c8; oacc[nj][3] *= c8;
        }

        // ---- P: C-layout -> smem -> A-layout fragments (per-warp buffer) ----
        #pragma unroll
        for (int nj = 0; nj < 4; nj++) {
            Ps[warp][g][nj * 8 + tg * 2]         = __float_as_uint(s[nj][0]);
            Ps[warp][g][nj * 8 + tg * 2 + 1]     = __float_as_uint(s[nj][1]);
            Ps[warp][g + 8][nj * 8 + tg * 2]     = __float_as_uint(s[nj][2]);
            Ps[warp][g + 8][nj * 8 + tg * 2 + 1] = __float_as_uint(s[nj][3]);
        }
        __syncwarp();
        unsigned pf[4][4];
        #pragma unroll
        for (int kc = 0; kc < 4; kc++) {
            pf[kc][0] = Ps[warp][g][kc * 8 + tg];
            pf[kc][1] = Ps[warp][g + 8][kc * 8 + tg];
            pf[kc][2] = Ps[warp][g][kc * 8 + tg + 4];
            pf[kc][3] = Ps[warp][g + 8][kc * 8 + tg + 4];
        }

        // ---- O += P(16x32) @ V(32x64) ----
        #pragma unroll
        for (int kc = 0; kc < 4; kc++) {
            unsigned vb[8][2];
            #pragma unroll
            for (int nj = 0; nj < 8; nj++) {
                int c = nj * 8 + g;
                vb[nj][0] = Vc[kc * 8 + tg][c];
                vb[nj][1] = Vc[kc * 8 + tg + 4][c];
            }
            #pragma unroll
            for (int nj = 0; nj < 8; nj++)
                mma_tf32(oacc[nj], pf[kc], vb[nj]);
        }

        __syncthreads();   // all warps done reading Kc/Vc
        if (it + 2 < 32) issue_kv(it + 2, Kc, Vc);   // refill the just-freed buffer
    }

    // ---- finalize: O /= l, write [b, q, h*64 + d] ----
    float i0 = 1.f / l0, i8 = 1.f / l8;
    float* Ob = O + (size_t)b * SQv * Dm + h * HDv;
    #pragma unroll
    for (int nj = 0; nj < 8; nj++) {
        int col = nj * 8 + tg * 2;
        *(float2*)&Ob[(size_t)row0 * Dm + col] =
            make_float2(oacc[nj][0] * i0, oacc[nj][1] * i0);
        *(float2*)&Ob[(size_t)(row0 + 8) * Dm + col] =
            make_float2(oacc[nj][2] * i8, oacc[nj][3] * i8);
    }
}

// ---------------- gated residual + post-LayerNorm (in-place on q) ----------------------
__global__ __launch_bounds__(256)
void addnorm_kernel(float* __restrict__ q, const float* __restrict__ delta,
                    const float* __restrict__ gate, const float* __restrict__ g,
                    const float* __restrict__ bb)
{
    const size_t row = blockIdx.x;
    const int tid = threadIdx.x;
    const float gt = gate[0];
    const float sp = (gt > 20.f) ? gt : log1pf(expf(gt));   // softplus

    float2 x = *(float2*)&q[row * Dm + tid * 2];
    float2 dd = *(const float2*)&delta[row * Dm + tid * 2];
    float y0 = x.x + sp * dd.x;
    float y1 = x.y + sp * dd.y;

    float s = blk_sum256(y0 + y1);
    float mu = s * (1.f / 512.f);
    float s2 = blk_sum256((y0 - mu) * (y0 - mu) + (y1 - mu) * (y1 - mu));
    float inv = rsqrtf(s2 * (1.f / 512.f) + 1e-5f);

    float2 o;
    o.x = (y0 - mu) * inv * g[tid * 2 + 0] + bb[tid * 2 + 0];
    o.y = (y1 - mu) * inv * g[tid * 2 + 1] + bb[tid * 2 + 1];
    *(float2*)&q[row * Dm + tid * 2] = o;
}

// ---------------- launcher -------------------------------------------------------------
extern "C" void kernel_launch(void* const* d_in, const int* in_sizes, int n_in,
                              void* d_out, int out_size)
{
    (void)in_sizes; (void)n_in; (void)out_size;
    const float* q_in  = (const float*)d_in[0];
    const float* k_in  = (const float*)d_in[1];
    const float* v_in  = (const float*)d_in[2];
    const float* WQ    = (const float*)d_in[3];
    const float* bQ    = (const float*)d_in[4];
    const float* WK    = (const float*)d_in[5];
    const float* bK    = (const float*)d_in[6];
    const float* WV    = (const float*)d_in[7];
    const float* bV    = (const float*)d_in[8];
    const float* WO    = (const float*)d_in[9];
    const float* bO    = (const float*)d_in[10];
    const float* Wf1   = (const float*)d_in[11];
    const float* bf1   = (const float*)d_in[12];
    const float* Wf2   = (const float*)d_in[13];
    const float* bf2   = (const float*)d_in[14];
    const float* ln1g  = (const float*)d_in[15];
    const float* ln1b  = (const float*)d_in[16];
    const float* ln2g  = (const float*)d_in[17];
    const float* ln2b  = (const float*)d_in[18];
    const float* scale = (const float*)d_in[19];
    const float* extra = (const float*)d_in[20];
    const float* gA    = (const float*)d_in[21];
    const float* gF    = (const float*)d_in[22];

    float *QH, *KH, *VH, *ATT, *F1, *S0;
    cudaGetSymbolAddress((void**)&QH, g_QH);
    cudaGetSymbolAddress((void**)&KH, g_KH);
    cudaGetSymbolAddress((void**)&VH, g_VH);
    cudaGetSymbolAddress((void**)&ATT, g_ATT);
    cudaGetSymbolAddress((void**)&F1, g_F1);
    cudaGetSymbolAddress((void**)&S0, g_S0);

    // opt-in to >48KB dynamic smem for the pipelined GEMM (host state, capture-safe)
    cudaFuncSetAttribute(gemm_tf32<0>, cudaFuncAttributeMaxDynamicSharedMemorySize, GEMM_SMEM);
    cudaFuncSetAttribute(gemm_tf32<1>, cudaFuncAttributeMaxDynamicSharedMemorySize, GEMM_SMEM);

    float* qbuf = (float*)d_out;   // q lives in d_out the whole time
    cudaMemcpyAsync(qbuf, q_in, (size_t)Mrows * Dm * sizeof(float),
                    cudaMemcpyDeviceToDevice);

    const dim3 gP(Dm / BN, Mrows / BM);        // (4, 64)  N=512 GEMMs
    const dim3 gF1(DFFv / BN, Mrows / BM);     // (16, 64) FFN1

    for (int i = 0; i < 2; i++) {
        const size_t wofD = (size_t)i * Dm * Dm;
        const size_t wofF = (size_t)i * Dm * DFFv;

        gemm_tf32<0><<<gP, 128, GEMM_SMEM>>>(qbuf, WQ + wofD, bQ + i * Dm, QH, Mrows, Dm, Dm);
        gemm_tf32<0><<<gP, 128, GEMM_SMEM>>>(k_in, WK + wofD, bK + i * Dm, KH, Mrows, Dm, Dm);
        gemm_tf32<0><<<gP, 128, GEMM_SMEM>>>(v_in, WV + wofD, bV + i * Dm, VH, Mrows, Dm, Dm);

        // fused scores(+prev/S0) + online softmax + P@V; attn-out overwrites QH
        const float* prev = (i == 0) ? nullptr : S0;
        float* Sout = (i == 0) ? S0 : nullptr;
        attn_fused<<<dim3(SQv / 64, Bz * Hh), 128>>>(QH, KH, VH, scale, extra, i,
                                                     prev, Sout, QH);

        gemm_tf32<0><<<gP, 128, GEMM_SMEM>>>(QH, WO + wofD, bO + i * Dm, ATT, Mrows, Dm, Dm);
        addnorm_kernel<<<Mrows, 256>>>(qbuf, ATT, gA + i, ln1g + (size_t)i * Dm, ln1b + (size_t)i * Dm);

        gemm_tf32<1><<<gF1, 128, GEMM_SMEM>>>(qbuf, Wf1 + wofF, bf1 + i * DFFv, F1, Mrows, DFFv, Dm);
        gemm_tf32<0><<<gP, 128, GEMM_SMEM>>>(F1, Wf2 + wofF, bf2 + i * Dm, ATT, Mrows, Dm, DFFv);
        addnorm_kernel<<<Mrows, 256>>>(qbuf, ATT, gF + i, ln2g + (size_t)i * Dm, ln2b + (size_t)i * Dm);
    }
}